// round 3
// baseline (speedup 1.0000x reference)
#include <cuda_runtime.h>

// ---------------------------------------------------------------------------
// Problem constants
// ---------------------------------------------------------------------------
#define TT   512
#define BB   1024
#define IN1  80
#define NH1  100
#define NG1  400
#define NH2  50
#define NG2  200

typedef unsigned long long ull;

// ---------------------------------------------------------------------------
// Device scratch
// ---------------------------------------------------------------------------
__device__ __align__(16) float g_pre1[(size_t)BB * TT * NG1];   // 838.9 MB
__device__ __align__(16) float g_h1  [(size_t)BB * TT * NH1];   // 209.7 MB
__device__ __align__(16) float g_pre2[(size_t)BB * TT * NG2];   // 419.4 MB

// gemm1 weights: blocked for 4-pair tiles: ull index (k*2+hf)*100 + 2*c + pos
__device__ __align__(16) float g_w1blk[IN1 * NG1];
__device__ __align__(16) float g_whh1T[NH1 * NG1];   // plain [k][g]
__device__ __align__(16) float g_wih2T[NH1 * NG2];   // plain [k][g]
__device__ __align__(16) float g_whh2T[NH2 * NG2];   // plain [k][g]
__device__ __align__(16) float g_b1[NG1];
__device__ __align__(16) float g_b2[NG2];

// ---------------------------------------------------------------------------
// f32x2 helpers (FFMA2 only reachable via PTX fma.rn.f32x2; bit-exact vs FFMA)
// ---------------------------------------------------------------------------
__device__ __forceinline__ ull ffma2(ull d, ull a, ull b) {
    asm("fma.rn.f32x2 %0, %1, %2, %0;" : "+l"(d) : "l"(a), "l"(b));
    return d;
}
__device__ __forceinline__ ull dup2(float x) {
    ull r; unsigned u = __float_as_uint(x);
    asm("mov.b64 %0, {%1, %1};" : "=l"(r) : "r"(u));
    return r;
}
__device__ __forceinline__ ull pk(float x, float y) {
    ull r;
    asm("mov.b64 %0, {%1, %2};" : "=l"(r) : "f"(x), "f"(y));
    return r;
}

// Fast-but-accurate activations (~1e-6 rel; NOT tanh.approx)
__device__ __forceinline__ float sigm(float x) {
    return __fdividef(1.0f, 1.0f + __expf(-x));
}
__device__ __forceinline__ float tanh_f(float x) {
    return __fdividef(2.0f, 1.0f + __expf(-2.0f * x)) - 1.0f;
}

// ---------------------------------------------------------------------------
// prep: transposes + layout blocking + bias fusion
// ---------------------------------------------------------------------------
__global__ void prep_kernel(const float* __restrict__ Wih1, const float* __restrict__ Whh1,
                            const float* __restrict__ bih1, const float* __restrict__ bhh1,
                            const float* __restrict__ Wih2, const float* __restrict__ Whh2,
                            const float* __restrict__ bih2, const float* __restrict__ bhh2) {
    int tid = blockIdx.x * blockDim.x + threadIdx.x;
    int stride = gridDim.x * blockDim.x;
    // gemm1 blocked: thread c owns pairs 4c..4c+3; g = 8c + 4hf + 2pos + e
    for (int i = tid; i < IN1 * NG1; i += stride) {
        int k = i / NG1, g = i % NG1;
        int c = g >> 3, rem = g & 7;
        int hf = rem >> 2, pos = (rem >> 1) & 1, e = rem & 1;
        g_w1blk[((k * 2 + hf) * 50 + c) * 4 + 2 * pos + e] = Wih1[g * IN1 + k];
    }
    for (int i = tid; i < NH1 * NG1; i += stride) { int k = i / NG1, g = i % NG1; g_whh1T[i] = Whh1[g * NH1 + k]; }
    for (int i = tid; i < NH1 * NG2; i += stride) { int k = i / NG2, g = i % NG2; g_wih2T[i] = Wih2[g * NH1 + k]; }
    for (int i = tid; i < NH2 * NG2; i += stride) { int k = i / NG2, g = i % NG2; g_whh2T[i] = Whh2[g * NH2 + k]; }
    for (int i = tid; i < NG1; i += stride) g_b1[i] = bih1[i] + bhh1[i];
    for (int i = tid; i < NG2; i += stride) g_b2[i] = bih2[i] + bhh2[i];
}

// ---------------------------------------------------------------------------
// gemm1: out[m][400] = x[m][80] @ w + b.  32 rows/CTA.
// 400 active threads = 8 row-groups(4 rows) x 50 col-threads(4 pairs).
// per k: 4 broadcast LDS.64 + 2 coalesced LDS.128 + 16 FFMA2.
// ---------------------------------------------------------------------------
__global__ __launch_bounds__(416, 1)
void gemm1_kernel(const float* __restrict__ x, const float* __restrict__ wblk,
                  const float* __restrict__ bias, float* __restrict__ out) {
    extern __shared__ float sm[];
    float* sw = sm;                        // 80*400 floats (blocked)
    ull*   sx = (ull*)(sm + IN1 * NG1);    // 32*80 dup pairs

    int tid = threadIdx.x;
    int m0  = blockIdx.x * 32;

    {
        const float4* src = (const float4*)wblk;
        float4*       dst = (float4*)sw;
        for (int i = tid; i < IN1 * NG1 / 4; i += 416) dst[i] = src[i];
    }
    for (int i = tid; i < 32 * IN1; i += 416)
        sx[i] = dup2(x[(size_t)(m0 + i / IN1) * IN1 + (i % IN1)]);
    __syncthreads();

    if (tid < 400) {
        int rg = tid / 50, cg = tid - rg * 50;
        int rb = rg * 4;
        const ull* swp = (const ull*)sw;

        ull acc[4][4];
        {
            ull b0 = pk(bias[8 * cg + 0], bias[8 * cg + 1]);
            ull b1 = pk(bias[8 * cg + 2], bias[8 * cg + 3]);
            ull b2 = pk(bias[8 * cg + 4], bias[8 * cg + 5]);
            ull b3 = pk(bias[8 * cg + 6], bias[8 * cg + 7]);
#pragma unroll
            for (int r = 0; r < 4; r++) { acc[r][0] = b0; acc[r][1] = b1; acc[r][2] = b2; acc[r][3] = b3; }
        }

#pragma unroll 4
        for (int k = 0; k < IN1; k++) {
            ulonglong2 w0 = *(const ulonglong2*)(swp + (k * 2 + 0) * 100 + 2 * cg);
            ulonglong2 w1 = *(const ulonglong2*)(swp + (k * 2 + 1) * 100 + 2 * cg);
#pragma unroll
            for (int r = 0; r < 4; r++) {
                ull xv = sx[(rb + r) * IN1 + k];
                acc[r][0] = ffma2(acc[r][0], xv, w0.x);
                acc[r][1] = ffma2(acc[r][1], xv, w0.y);
                acc[r][2] = ffma2(acc[r][2], xv, w1.x);
                acc[r][3] = ffma2(acc[r][3], xv, w1.y);
            }
        }
#pragma unroll
        for (int r = 0; r < 4; r++) {
            ull* o = (ull*)(out + (size_t)(m0 + rb + r) * NG1 + 8 * cg);
            *(ulonglong2*)(o)     = make_ulonglong2(acc[r][0], acc[r][1]);
            *(ulonglong2*)(o + 2) = make_ulonglong2(acc[r][2], acc[r][3]);
        }
    }
}

// ---------------------------------------------------------------------------
// gemm2: out[m][200] = h1[m][100] @ w + b.  32 rows/CTA, 2 CTAs/SM.
// 400 active threads = 8 row-groups(4 rows) x 50 col-threads(2 pairs).
// per k: 4 broadcast LDS.64 + 1 coalesced LDS.128 + 8 FFMA2.
// ---------------------------------------------------------------------------
__global__ __launch_bounds__(416, 2)
void gemm2_kernel(const float* __restrict__ x, const float* __restrict__ wT,
                  const float* __restrict__ bias, float* __restrict__ out) {
    extern __shared__ float sm[];
    float* sw = sm;                        // 100*200 floats (plain [k][g])
    ull*   sx = (ull*)(sm + NH1 * NG2);    // 32*100 dup pairs

    int tid = threadIdx.x;
    int m0  = blockIdx.x * 32;

    {
        const float4* src = (const float4*)wT;
        float4*       dst = (float4*)sw;
        for (int i = tid; i < NH1 * NG2 / 4; i += 416) dst[i] = src[i];
    }
    for (int i = tid; i < 32 * NH1; i += 416)
        sx[i] = dup2(x[(size_t)(m0 + i / NH1) * NH1 + (i % NH1)]);
    __syncthreads();

    if (tid < 400) {
        int rg = tid / 50, cg = tid - rg * 50;
        int rb = rg * 4;
        const ull* swp = (const ull*)sw;   // 100 ull per k-row

        ull acc[4][2];
        {
            ull b0 = pk(bias[4 * cg + 0], bias[4 * cg + 1]);
            ull b1 = pk(bias[4 * cg + 2], bias[4 * cg + 3]);
#pragma unroll
            for (int r = 0; r < 4; r++) { acc[r][0] = b0; acc[r][1] = b1; }
        }

#pragma unroll 4
        for (int k = 0; k < NH1; k++) {
            ulonglong2 w = *(const ulonglong2*)(swp + k * 100 + 2 * cg);
#pragma unroll
            for (int r = 0; r < 4; r++) {
                ull xv = sx[(rb + r) * NH1 + k];
                acc[r][0] = ffma2(acc[r][0], xv, w.x);
                acc[r][1] = ffma2(acc[r][1], xv, w.y);
            }
        }
#pragma unroll
        for (int r = 0; r < 4; r++)
            *(ulonglong2*)(out + (size_t)(m0 + rb + r) * NG2 + 4 * cg) =
                make_ulonglong2(acc[r][0], acc[r][1]);
    }
}

// ---------------------------------------------------------------------------
// Persistent LSTM: NB=8 batch rows/CTA, WhhT in smem.
// Gate phase: NACT threads = 4 row-groups(2 rows) x NCG col-threads(2 pairs).
//   per k: 2 broadcast LDS.64 (dup h) + 1 coalesced LDS.128 (w) + 4 FFMA2.
// Update phase: NACT threads x 2 units; c in registers.
// ---------------------------------------------------------------------------
template<int H, bool LAST_ONLY>
__global__ __launch_bounds__(416, 1)
void lstm_kernel(const float* __restrict__ pre, const float* __restrict__ whhT,
                 float* __restrict__ hout) {
    constexpr int G    = 4 * H;
    constexpr int NP   = G / 2;     // ull pairs per gate row (200 / 100)
    constexpr int NCG  = NP / 2;    // col-threads (100 / 50)
    constexpr int NACT = 4 * NCG;   // active threads (400 / 200)

    extern __shared__ float sm[];
    float* sw  = sm;                      // H*G floats (WhhT, plain [k][g])
    float* sgf = sm + H * G;              // 8*G floats (gates staging)
    ull*   sgu = (ull*)sgf;
    ull*   shd = (ull*)(sgf + 8 * G);     // 8*H dup'd h

    int tid = threadIdx.x;
    int b0  = blockIdx.x * 8;

    for (int i = tid; i < H * G; i += blockDim.x) sw[i] = whhT[i];
    for (int i = tid; i < 8 * H; i += blockDim.x) shd[i] = 0ULL;
    __syncthreads();

    bool gate = (tid < NACT);
    int rg = 0, cg = 0;
    if (gate) { rg = tid / NCG; cg = tid - rg * NCG; }
    int rb = rg * 2;
    const ull* swp = (const ull*)sw;

    // update-phase unit mapping (fixed per thread): units tid and tid+NACT
    int ur[2], uj[2];
    {
        int u0 = tid, u1 = tid + NACT;
        ur[0] = u0 / H; uj[0] = u0 - ur[0] * H;
        ur[1] = u1 / H; uj[1] = u1 - ur[1] * H;
    }
    float cst[2] = {0.0f, 0.0f};

    ull pn[2][2];
    if (gate) {
#pragma unroll
        for (int r = 0; r < 2; r++) {
            const float4 v = *(const float4*)(pre + ((size_t)(b0 + rb + r) * TT) * G + 4 * cg);
            pn[r][0] = pk(v.x, v.y); pn[r][1] = pk(v.z, v.w);
        }
    }

    for (int t = 0; t < TT; t++) {
        if (gate) {
            ull acc[2][2];
#pragma unroll
            for (int r = 0; r < 2; r++) { acc[r][0] = pn[r][0]; acc[r][1] = pn[r][1]; }

            int tn = (t + 1 < TT) ? t + 1 : t;
#pragma unroll
            for (int r = 0; r < 2; r++) {
                const float4 v = *(const float4*)(pre + ((size_t)(b0 + rb + r) * TT + tn) * G + 4 * cg);
                pn[r][0] = pk(v.x, v.y); pn[r][1] = pk(v.z, v.w);
            }

#pragma unroll 4
            for (int k = 0; k < H; k++) {
                ulonglong2 w = *(const ulonglong2*)(swp + k * NP + 2 * cg);
                ull h0 = shd[(rb + 0) * H + k];
                ull h1 = shd[(rb + 1) * H + k];
                acc[0][0] = ffma2(acc[0][0], h0, w.x);
                acc[0][1] = ffma2(acc[0][1], h0, w.y);
                acc[1][0] = ffma2(acc[1][0], h1, w.x);
                acc[1][1] = ffma2(acc[1][1], h1, w.y);
            }
#pragma unroll
            for (int r = 0; r < 2; r++)
                *(ulonglong2*)(sgu + (rb + r) * NP + 2 * cg) =
                    make_ulonglong2(acc[r][0], acc[r][1]);
        }
        __syncthreads();

        if (tid < NACT) {
#pragma unroll
            for (int u = 0; u < 2; u++) {
                int r = ur[u], j = uj[u];
                const float* gr = sgf + r * G;
                float ig = sigm(gr[j]);
                float fg = sigm(gr[H + j]);
                float gg = tanh_f(gr[2 * H + j]);
                float og = sigm(gr[3 * H + j]);
                float c  = fg * cst[u] + ig * gg;
                cst[u] = c;
                float h  = og * tanh_f(c);
                shd[r * H + j] = dup2(h);
                if (!LAST_ONLY) {
                    hout[((size_t)(b0 + r) * TT + t) * H + j] = h;
                } else if (t == TT - 1) {
                    hout[(size_t)(b0 + r) * H + j] = h;
                }
            }
        }
        __syncthreads();
    }
}

// ---------------------------------------------------------------------------
// Launch
// ---------------------------------------------------------------------------
extern "C" void kernel_launch(void* const* d_in, const int* in_sizes, int n_in,
                              void* d_out, int out_size) {
    const float* x    = (const float*)d_in[0];
    const float* Wih1 = (const float*)d_in[1];
    const float* Whh1 = (const float*)d_in[2];
    const float* bih1 = (const float*)d_in[3];
    const float* bhh1 = (const float*)d_in[4];
    const float* Wih2 = (const float*)d_in[5];
    const float* Whh2 = (const float*)d_in[6];
    const float* bih2 = (const float*)d_in[7];
    const float* bhh2 = (const float*)d_in[8];
    float* out = (float*)d_out;
    (void)in_sizes; (void)n_in; (void)out_size;

    void *pre1, *h1, *pre2, *w1blk, *whh1T, *wih2T, *whh2T, *b1, *b2;
    cudaGetSymbolAddress(&pre1,  g_pre1);
    cudaGetSymbolAddress(&h1,    g_h1);
    cudaGetSymbolAddress(&pre2,  g_pre2);
    cudaGetSymbolAddress(&w1blk, g_w1blk);
    cudaGetSymbolAddress(&whh1T, g_whh1T);
    cudaGetSymbolAddress(&wih2T, g_wih2T);
    cudaGetSymbolAddress(&whh2T, g_whh2T);
    cudaGetSymbolAddress(&b1,    g_b1);
    cudaGetSymbolAddress(&b2,    g_b2);

    const int SMEM_G1 = IN1 * NG1 * 4 + 32 * IN1 * 8;               // 148480
    const int SMEM_G2 = NH1 * NG2 * 4 + 32 * NH1 * 8;               // 105600
    const int SMEM_L1 = NH1 * NG1 * 4 + 8 * NG1 * 4 + 8 * NH1 * 8;  // 179200
    const int SMEM_L2 = NH2 * NG2 * 4 + 8 * NG2 * 4 + 8 * NH2 * 8;  // 49600

    cudaFuncSetAttribute(gemm1_kernel, cudaFuncAttributeMaxDynamicSharedMemorySize, SMEM_G1);
    cudaFuncSetAttribute(gemm2_kernel, cudaFuncAttributeMaxDynamicSharedMemorySize, SMEM_G2);
    cudaFuncSetAttribute(lstm_kernel<NH1, false>, cudaFuncAttributeMaxDynamicSharedMemorySize, SMEM_L1);
    cudaFuncSetAttribute(lstm_kernel<NH2, true>,  cudaFuncAttributeMaxDynamicSharedMemorySize, SMEM_L2);

    prep_kernel<<<96, 256>>>(Wih1, Whh1, bih1, bhh1, Wih2, Whh2, bih2, bhh2);

    gemm1_kernel<<<BB * TT / 32, 416, SMEM_G1>>>(
        x, (const float*)w1blk, (const float*)b1, (float*)pre1);

    lstm_kernel<NH1, false><<<BB / 8, 416, SMEM_L1>>>(
        (const float*)pre1, (const float*)whh1T, (float*)h1);

    gemm2_kernel<<<BB * TT / 32, 416, SMEM_G2>>>(
        (const float*)h1, (const float*)wih2T, (const float*)b2, (float*)pre2);

    lstm_kernel<NH2, true><<<BB / 8, 224, SMEM_L2>>>(
        (const float*)pre2, (const float*)whh2T, out);
}

// round 4
// speedup vs baseline: 1.4620x; 1.4620x over previous
#include <cuda_runtime.h>

// ---------------------------------------------------------------------------
// Problem constants
// ---------------------------------------------------------------------------
#define TT   512
#define BB   1024
#define IN1  80
#define NH1  100
#define NG1  400
#define NH2  50
#define NG2  200

typedef unsigned long long ull;

// ---------------------------------------------------------------------------
// Device scratch
// ---------------------------------------------------------------------------
__device__ __align__(16) float g_pre1[(size_t)BB * TT * NG1];   // [b][t][400]
__device__ __align__(16) float g_h1  [(size_t)BB * TT * NH1];   // [b][t][100]
__device__ __align__(16) float g_pre2[(size_t)BB * TT * NG2];   // [b][t][200]

// GEMM weights: [k][pair(padded)][2] floats (pair-interleaved, zero-padded)
__device__ __align__(16) float g_w1p[IN1 * 208 * 2];   // 80 k x 208 pairs
__device__ __align__(16) float g_w2p[NH1 * 104 * 2];   // 100 k x 104 pairs
// LSTM recurrent weights: plain [k][g]
__device__ __align__(16) float g_whh1T[NH1 * NG1];
__device__ __align__(16) float g_whh2T[NH2 * NG2];
// Fused biases, zero-padded
__device__ __align__(16) float g_b1[512];
__device__ __align__(16) float g_b2[512];

// ---------------------------------------------------------------------------
// f32x2 helpers (FFMA2 via PTX fma.rn.f32x2; bit-exact vs scalar FFMA)
// ---------------------------------------------------------------------------
__device__ __forceinline__ ull ffma2(ull d, ull a, ull b) {
    asm("fma.rn.f32x2 %0, %1, %2, %0;" : "+l"(d) : "l"(a), "l"(b));
    return d;
}
__device__ __forceinline__ ull dup2(float x) {
    ull r; unsigned u = __float_as_uint(x);
    asm("mov.b64 %0, {%1, %1};" : "=l"(r) : "r"(u));
    return r;
}
__device__ __forceinline__ ull pk(float x, float y) {
    ull r;
    asm("mov.b64 %0, {%1, %2};" : "=l"(r) : "f"(x), "f"(y));
    return r;
}

// Accurate fast activations (~1e-6 rel; NOT tanh.approx)
__device__ __forceinline__ float sigm(float x) {
    return __fdividef(1.0f, 1.0f + __expf(-x));
}
__device__ __forceinline__ float tanh_f(float x) {
    return __fdividef(2.0f, 1.0f + __expf(-2.0f * x)) - 1.0f;
}

// ---------------------------------------------------------------------------
// prep: build padded pair-interleaved GEMM weights, plain LSTM weights, biases
// ---------------------------------------------------------------------------
__global__ void prep_kernel(const float* __restrict__ Wih1, const float* __restrict__ Whh1,
                            const float* __restrict__ bih1, const float* __restrict__ bhh1,
                            const float* __restrict__ Wih2, const float* __restrict__ Whh2,
                            const float* __restrict__ bih2, const float* __restrict__ bhh2) {
    int tid = blockIdx.x * blockDim.x + threadIdx.x;
    int stride = gridDim.x * blockDim.x;

    for (int i = tid; i < IN1 * 208 * 2; i += stride) {
        int k = i / (208 * 2), rem = i % (208 * 2);
        int g = rem;                       // g = 2*pair + e = col index
        g_w1p[i] = (g < NG1) ? Wih1[g * IN1 + k] : 0.0f;
    }
    for (int i = tid; i < NH1 * 104 * 2; i += stride) {
        int k = i / (104 * 2), rem = i % (104 * 2);
        int g = rem;
        g_w2p[i] = (g < NG2) ? Wih2[g * NH1 + k] : 0.0f;
    }
    for (int i = tid; i < NH1 * NG1; i += stride) { int k = i / NG1, g = i % NG1; g_whh1T[i] = Whh1[g * NH1 + k]; }
    for (int i = tid; i < NH2 * NG2; i += stride) { int k = i / NG2, g = i % NG2; g_whh2T[i] = Whh2[g * NH2 + k]; }
    for (int i = tid; i < 512; i += stride) {
        g_b1[i] = (i < NG1) ? bih1[i] + bhh1[i] : 0.0f;
        g_b2[i] = (i < NG2) ? bih2[i] + bhh2[i] : 0.0f;
    }
}

// ---------------------------------------------------------------------------
// GEMM: out[m][GR] = x[m][K] @ W + b.   CTA tile M=128, 13 warps.
// Lane l owns rows 4l..4l+3 (one coalesced LDS.128 for x per k).
// Warp owns an 8-pair col chunk (4 broadcast LDS.128 for w per k).
// => 8 wavefronts per 32 FFMA2 warp-instrs: FFMA2-bound.
// ---------------------------------------------------------------------------
template<int K, int GR, int PADP, int CH>
__global__ __launch_bounds__(416, 1)
void gemm_kernel(const float* __restrict__ x, const float* __restrict__ wp,
                 const float* __restrict__ bias, float* __restrict__ out) {
    constexpr int XP = 132;                    // padded row-dim for x tile
    extern __shared__ float sm[];
    float* swf = sm;                           // K*PADP*2 floats (pair-interleaved w)
    float* sx  = sm + K * PADP * 2;            // [k][132] transposed x tile

    int tid  = threadIdx.x;
    int lane = tid & 31;
    int wi   = tid >> 5;
    int m0   = blockIdx.x * 128;

    {   // weights: straight float4 copy
        const float4* src = (const float4*)wp;
        float4*       dst = (float4*)swf;
        for (int i = tid; i < K * PADP / 2; i += 416) dst[i] = src[i];
    }
    // x tile transposed: read coalesced, write [k][row] (4-way conflict, cheap)
    for (int i = tid; i < 128 * K; i += 416) {
        int r = i / K, k = i - r * K;
        sx[k * XP + r] = x[(size_t)(m0 + r) * K + k];
    }
    __syncthreads();

    const ull* swp = (const ull*)swf;          // [k][PADP] pairs

#pragma unroll
    for (int it = 0; it < CH; it++) {
        int ci = it * 13 + wi;
        int p0 = ci * 8;                       // first pair of this chunk
        if (p0 >= GR / 2 + (PADP - GR / 2)) {} // (no-op; chunks bounded below)
        if (p0 + 0 >= PADP) continue;
        bool any_real = (2 * p0 < GR);
        if (!any_real) continue;

        ull acc[4][8];
        {
#pragma unroll
            for (int j = 0; j < 8; j++) {
                ull b = pk(bias[2 * (p0 + j)], bias[2 * (p0 + j) + 1]);
#pragma unroll
                for (int r = 0; r < 4; r++) acc[r][j] = b;
            }
        }

#pragma unroll 4
        for (int k = 0; k < K; k++) {
            float4 xv = *(const float4*)(sx + k * XP + 4 * lane);
            ull xd0 = dup2(xv.x), xd1 = dup2(xv.y), xd2 = dup2(xv.z), xd3 = dup2(xv.w);
            const ull* wr = swp + (size_t)k * PADP + p0;
            ulonglong2 w01 = *(const ulonglong2*)(wr + 0);
            ulonglong2 w23 = *(const ulonglong2*)(wr + 2);
            ulonglong2 w45 = *(const ulonglong2*)(wr + 4);
            ulonglong2 w67 = *(const ulonglong2*)(wr + 6);
            ull wv[8] = {w01.x, w01.y, w23.x, w23.y, w45.x, w45.y, w67.x, w67.y};
#pragma unroll
            for (int j = 0; j < 8; j++) {
                acc[0][j] = ffma2(acc[0][j], xd0, wv[j]);
                acc[1][j] = ffma2(acc[1][j], xd1, wv[j]);
                acc[2][j] = ffma2(acc[2][j], xd2, wv[j]);
                acc[3][j] = ffma2(acc[3][j], xd3, wv[j]);
            }
        }

#pragma unroll
        for (int r = 0; r < 4; r++) {
            size_t m = (size_t)(m0 + 4 * lane + r);
#pragma unroll
            for (int j = 0; j < 8; j++) {
                int pair = p0 + j;
                if (2 * pair < GR)
                    *(ull*)(out + m * GR + 2 * pair) = acc[r][j];
            }
        }
    }
}

// ---------------------------------------------------------------------------
// Persistent LSTM, 8 batch rows/CTA, 128 CTAs.
// Gate phase (tid<200): thread = (rg in {0,1} -> rows 4rg..4rg+3, cg -> PPT cols).
//   Row-pair packed FFMA2: a = (h[k][r0],h[k][r1]) bcast LDS.64 from h[k][rows10],
//   b = dup(w[k][c]) from coalesced float4/float2. 6 wf per 8 FFMA2 (PPT=4).
// Update phase (tid<200): UPT units each, j-fastest for coalesced writes.
// ---------------------------------------------------------------------------
template<int H, int PPT, bool LAST_ONLY>
__global__ __launch_bounds__(224, 1)
void lstm_kernel(const float* __restrict__ pre, const float* __restrict__ whhT,
                 float* __restrict__ hout) {
    constexpr int G    = 4 * H;
    constexpr int NCG  = G / PPT;          // 100 for both layers
    constexpr int NACT = 2 * NCG;          // 200
    constexpr int UPT  = 8 * H / NACT;     // 4 (H=100) / 2 (H=50)
    constexpr int RP   = 10;               // padded row-slot dim

    extern __shared__ float sm[];
    float* sw  = sm;                       // [H][G] recurrent weights
    float* sgt = sm + H * G;               // [G][RP] gate staging (transposed)
    float* shp = sgt + G * RP;             // [H][RP] h (row-packed)

    int tid = threadIdx.x;
    int b0  = blockIdx.x * 8;

    for (int i = tid; i < H * G; i += blockDim.x) sw[i] = whhT[i];
    for (int i = tid; i < H * RP; i += blockDim.x) shp[i] = 0.0f;
    __syncthreads();

    bool gate = (tid < NACT);
    int rg = 0, cg = 0;
    if (gate) { rg = tid / NCG; cg = tid - rg * NCG; }
    int r0 = 4 * rg;
    int c0 = PPT * cg;

    // update mapping: units u = tid + i*NACT; r = u/H, j = u%H  (j fastest)
    int ur[UPT], uj[UPT];
#pragma unroll
    for (int i = 0; i < UPT; i++) {
        int u = tid + i * NACT;
        ur[i] = u / H; uj[i] = u - ur[i] * H;
    }
    float cst[UPT];
#pragma unroll
    for (int i = 0; i < UPT; i++) cst[i] = 0.0f;

    // prefetched pre values: pv[r][j], rows r0..r0+3, cols c0..c0+PPT-1
    float pv[4][PPT];
    if (gate) {
#pragma unroll
        for (int r = 0; r < 4; r++) {
            const float* src = pre + ((size_t)(b0 + r0 + r) * TT) * G + c0;
            if (PPT == 4) { float4 v = *(const float4*)src; pv[r][0]=v.x; pv[r][1]=v.y; pv[r][2]=v.z; pv[r][3]=v.w; }
            else          { float2 v = *(const float2*)src; pv[r][0]=v.x; pv[r][1]=v.y; }
        }
    }

    for (int t = 0; t < TT; t++) {
        if (gate) {
            ull acc[2][PPT];
#pragma unroll
            for (int j = 0; j < PPT; j++) {
                acc[0][j] = pk(pv[0][j], pv[1][j]);
                acc[1][j] = pk(pv[2][j], pv[3][j]);
            }
            // prefetch next timestep
            int tn = (t + 1 < TT) ? t + 1 : t;
#pragma unroll
            for (int r = 0; r < 4; r++) {
                const float* src = pre + ((size_t)(b0 + r0 + r) * TT + tn) * G + c0;
                if (PPT == 4) { float4 v = *(const float4*)src; pv[r][0]=v.x; pv[r][1]=v.y; pv[r][2]=v.z; pv[r][3]=v.w; }
                else          { float2 v = *(const float2*)src; pv[r][0]=v.x; pv[r][1]=v.y; }
            }

#pragma unroll 4
            for (int k = 0; k < H; k++) {
                ull hA = *(const ull*)(shp + k * RP + r0);       // rows r0,r0+1
                ull hB = *(const ull*)(shp + k * RP + r0 + 2);   // rows r0+2,r0+3
                const float* wr = sw + k * G + c0;
                float wf[PPT];
                if (PPT == 4) { float4 v = *(const float4*)wr; wf[0]=v.x; wf[1]=v.y; wf[2]=v.z; wf[3]=v.w; }
                else          { float2 v = *(const float2*)wr; wf[0]=v.x; wf[1]=v.y; }
#pragma unroll
                for (int j = 0; j < PPT; j++) {
                    ull wd = dup2(wf[j]);
                    acc[0][j] = ffma2(acc[0][j], hA, wd);
                    acc[1][j] = ffma2(acc[1][j], hB, wd);
                }
            }
#pragma unroll
            for (int j = 0; j < PPT; j++) {
                *(ull*)(sgt + (c0 + j) * RP + r0)     = acc[0][j];
                *(ull*)(sgt + (c0 + j) * RP + r0 + 2) = acc[1][j];
            }
        }
        __syncthreads();

        if (tid < NACT) {
#pragma unroll
            for (int i = 0; i < UPT; i++) {
                int r = ur[i], j = uj[i];
                float ig = sigm(sgt[(0 * H + j) * RP + r]);
                float fg = sigm(sgt[(1 * H + j) * RP + r]);
                float gg = tanh_f(sgt[(2 * H + j) * RP + r]);
                float og = sigm(sgt[(3 * H + j) * RP + r]);
                float c  = fg * cst[i] + ig * gg;
                cst[i] = c;
                float h  = og * tanh_f(c);
                shp[j * RP + r] = h;
                if (!LAST_ONLY) {
                    hout[((size_t)(b0 + r) * TT + t) * H + j] = h;
                } else if (t == TT - 1) {
                    hout[(size_t)(b0 + r) * H + j] = h;
                }
            }
        }
        __syncthreads();
    }
}

// ---------------------------------------------------------------------------
// Launch
// ---------------------------------------------------------------------------
extern "C" void kernel_launch(void* const* d_in, const int* in_sizes, int n_in,
                              void* d_out, int out_size) {
    const float* x    = (const float*)d_in[0];
    const float* Wih1 = (const float*)d_in[1];
    const float* Whh1 = (const float*)d_in[2];
    const float* bih1 = (const float*)d_in[3];
    const float* bhh1 = (const float*)d_in[4];
    const float* Wih2 = (const float*)d_in[5];
    const float* Whh2 = (const float*)d_in[6];
    const float* bih2 = (const float*)d_in[7];
    const float* bhh2 = (const float*)d_in[8];
    float* out = (float*)d_out;
    (void)in_sizes; (void)n_in; (void)out_size;

    void *pre1, *h1, *pre2, *w1p, *w2p, *whh1T, *whh2T, *b1, *b2;
    cudaGetSymbolAddress(&pre1,  g_pre1);
    cudaGetSymbolAddress(&h1,    g_h1);
    cudaGetSymbolAddress(&pre2,  g_pre2);
    cudaGetSymbolAddress(&w1p,   g_w1p);
    cudaGetSymbolAddress(&w2p,   g_w2p);
    cudaGetSymbolAddress(&whh1T, g_whh1T);
    cudaGetSymbolAddress(&whh2T, g_whh2T);
    cudaGetSymbolAddress(&b1,    g_b1);
    cudaGetSymbolAddress(&b2,    g_b2);

    const int SMEM_G1 = IN1 * 208 * 2 * 4 + IN1 * 132 * 4;            // 175360
    const int SMEM_G2 = NH1 * 104 * 2 * 4 + NH1 * 132 * 4;            // 136000
    const int SMEM_L1 = NH1 * NG1 * 4 + NG1 * 10 * 4 + NH1 * 10 * 4;  // 180000
    const int SMEM_L2 = NH2 * NG2 * 4 + NG2 * 10 * 4 + NH2 * 10 * 4;  //  50000

    cudaFuncSetAttribute(gemm_kernel<IN1, NG1, 208, 2>, cudaFuncAttributeMaxDynamicSharedMemorySize, SMEM_G1);
    cudaFuncSetAttribute(gemm_kernel<NH1, NG2, 104, 1>, cudaFuncAttributeMaxDynamicSharedMemorySize, SMEM_G2);
    cudaFuncSetAttribute(lstm_kernel<NH1, 4, false>, cudaFuncAttributeMaxDynamicSharedMemorySize, SMEM_L1);
    cudaFuncSetAttribute(lstm_kernel<NH2, 2, true>,  cudaFuncAttributeMaxDynamicSharedMemorySize, SMEM_L2);

    prep_kernel<<<96, 256>>>(Wih1, Whh1, bih1, bhh1, Wih2, Whh2, bih2, bhh2);

    gemm_kernel<IN1, NG1, 208, 2><<<BB * TT / 128, 416, SMEM_G1>>>(
        x, (const float*)w1p, (const float*)b1, (float*)pre1);

    lstm_kernel<NH1, 4, false><<<BB / 8, 224, SMEM_L1>>>(
        (const float*)pre1, (const float*)whh1T, (float*)h1);

    gemm_kernel<NH1, NG2, 104, 1><<<BB * TT / 128, 416, SMEM_G2>>>(
        (const float*)h1, (const float*)w2p, (const float*)b2, (float*)pre2);

    lstm_kernel<NH2, 2, true><<<BB / 8, 224, SMEM_L2>>>(
        (const float*)pre2, (const float*)whh2T, out);
}